// round 17
// baseline (speedup 1.0000x reference)
#include <cuda_runtime.h>
#include <math.h>

// BalancedAveragedHausdorffLoss, single fused kernel, v11.
// 128 blocks = (item, quarter), 1024 threads. Front end compressed:
// float4 loads (2 x LDG.128/thread), ballot-free row-mask assembly via
// shfl_xor OR-reduction (each warp owns exactly 2 rows), mask bits read
// back from the row masks in phase 2. Phase 2 = on-the-fly bitdist with
// r<=2 vote-free unroll + rare vote continuation. Last-block finalize.

#define ITEMS 32
#define Wdim  64
#define HW    4096
#define GINF  127   // GINF^2 = 16129

#define NT    1024
#define NWARP 32

__device__ float        g_t1[4 * ITEMS];   // term1 partial [item*4 + q]
__device__ float        g_t2[4 * ITEMS];   // term2 partial
__device__ int          g_ct[4 * ITEMS];   // n_t partial
__device__ int          g_cp[4 * ITEMS];   // n_p partial
__device__ unsigned int g_done;            // 0 at start; reset by last block

// nearest-set-bit distance from position p in 64-bit mask M (GINF if none)
__device__ __forceinline__ int bitdist(unsigned long long M, int p) {
    unsigned long long U = M >> p;
    unsigned long long V = M << (63 - p);
    int dDown = U ? (__ffsll((long long)U) - 1) : GINF;
    int dUp   = V ? __clzll((long long)V)      : GINF;
    return min(dDown, dUp);
}
__device__ __forceinline__ int bd2(unsigned long long M, int p) {
    int h = bitdist(M, p);
    return h * h;
}

__global__ __launch_bounds__(NT)
void bahl_fused_kernel(const float* __restrict__ pred,
                       const float* __restrict__ target,
                       float* __restrict__ out)
{
    __shared__ unsigned long long prmask[Wdim];  // pred-mask bits per row
    __shared__ unsigned long long trmask[Wdim];  // target-mask bits per row
    __shared__ float s1[NWARP], s2[NWARP];
    __shared__ int   sct[NWARP], scp[NWARP];

    const int bi      = blockIdx.x;
    const int item    = bi >> 2;
    const int quarter = bi & 3;
    const int tid     = threadIdx.x;
    const int wid     = tid >> 5;
    const int lid     = tid & 31;

    const float4* pb4 = (const float4*)(pred   + item * HW);
    const float4* tb4 = (const float4*)(target + item * HW);
    const float THR = 0.30001f;

    // --- Vectorized load: thread covers pixels 4*tid .. 4*tid+3 ---------
    float4 p4 = __ldg(&pb4[tid]);
    float4 t4 = __ldg(&tb4[tid]);
    unsigned pn = 0, tn = 0;   // 4-bit nibbles
    pn |= (fabsf(p4.x - 1.0f) <= THR) ? 1u : 0u;
    pn |= (fabsf(p4.y - 1.0f) <= THR) ? 2u : 0u;
    pn |= (fabsf(p4.z - 1.0f) <= THR) ? 4u : 0u;
    pn |= (fabsf(p4.w - 1.0f) <= THR) ? 8u : 0u;
    tn |= (t4.x != 0.0f) ? 1u : 0u;
    tn |= (t4.y != 0.0f) ? 2u : 0u;
    tn |= (t4.z != 0.0f) ? 4u : 0u;
    tn |= (t4.w != 0.0f) ? 8u : 0u;

    // --- Row-mask assembly: warp wid owns rows 2*wid (lanes 0-15) and
    // 2*wid+1 (lanes 16-31). OR-reduce 64-bit contributions over each
    // 16-lane half (xor offsets 1,2,4,8 stay within the half).
    unsigned long long pc = ((unsigned long long)pn) << (4 * (lid & 15));
    unsigned long long tc = ((unsigned long long)tn) << (4 * (lid & 15));
    #pragma unroll
    for (int o = 8; o > 0; o >>= 1) {
        pc |= __shfl_xor_sync(0xffffffffu, pc, o);
        tc |= __shfl_xor_sync(0xffffffffu, tc, o);
    }
    if (lid == 0)  { prmask[2 * wid]     = pc; trmask[2 * wid]     = tc; }
    if (lid == 16) { prmask[2 * wid + 1] = pc; trmask[2 * wid + 1] = tc; }
    __syncthreads();   // masks complete

    // --- Phase 2: one pixel per thread, h^2 on the fly -------------------
    const int pix = quarter * NT + tid;
    const int x = pix >> 6;
    const int y = pix & 63;

    const unsigned long long Mt = trmask[x];
    const unsigned long long Mp = prmask[x];
    const unsigned tmbit = (unsigned)((Mt >> y) & 1ULL);
    const unsigned pmbit = (unsigned)((Mp >> y) & 1ULL);

    int dt = bd2(Mt, y);          // r = 0 (own row)
    int dp = bd2(Mp, y);

    #pragma unroll
    for (int r = 1; r <= 2; r++) {   // vote-free exact updates
        const int rr = r * r;
        const int xu = x - r, xd = x + r;
        if (xu >= 0) {
            dt = min(dt, rr + bd2(trmask[xu], y));
            dp = min(dp, rr + bd2(prmask[xu], y));
        }
        if (xd < Wdim) {
            dt = min(dt, rr + bd2(trmask[xd], y));
            dp = min(dp, rr + bd2(prmask[xd], y));
        }
    }
    if (__any_sync(0xffffffffu, 9 < max(dt, dp))) {   // rare continuation
        #pragma unroll 1
        for (int r = 3; r < Wdim; r++) {
            const int rr = r * r;
            if (!__any_sync(0xffffffffu, rr < max(dt, dp))) break;
            const int xu = x - r, xd = x + r;
            if (xu >= 0) {
                dt = min(dt, rr + bd2(trmask[xu], y));
                dp = min(dp, rr + bd2(prmask[xu], y));
            }
            if (xd < Wdim) {
                dt = min(dt, rr + bd2(trmask[xd], y));
                dp = min(dp, rr + bd2(prmask[xd], y));
            }
        }
    }
    float a1 = pmbit ? sqrtf((float)dt) : 0.0f;   // term1: pred px -> target
    float a2 = tmbit ? sqrtf((float)dp) : 0.0f;   // term2: target px -> pred
    int   ct = __reduce_add_sync(0xffffffffu, (int)tmbit);
    int   cp = __reduce_add_sync(0xffffffffu, (int)pmbit);

    // --- Block reduction (32 warps) --------------------------------------
    #pragma unroll
    for (int o = 16; o > 0; o >>= 1) {
        a1 += __shfl_xor_sync(0xffffffffu, a1, o);
        a2 += __shfl_xor_sync(0xffffffffu, a2, o);
    }
    if (lid == 0) { s1[wid] = a1; s2[wid] = a2; sct[wid] = ct; scp[wid] = cp; }
    __syncthreads();

    int isLast = 0;
    if (tid == 0) {
        float t1 = 0.0f, t2 = 0.0f; int tC = 0, pC = 0;
        #pragma unroll
        for (int w = 0; w < NWARP; w++) {
            t1 += s1[w]; t2 += s2[w]; tC += sct[w]; pC += scp[w];
        }
        g_t1[bi] = t1; g_t2[bi] = t2; g_ct[bi] = tC; g_cp[bi] = pC;
        __threadfence();
        unsigned old = atomicAdd(&g_done, 1u);
        isLast = (old == 4 * ITEMS - 1) ? 1 : 0;
    }
    // Warp-0-only handoff (tid 0 is in warp 0; no extra block barrier).
    if (wid == 0) {
        isLast = __shfl_sync(0xffffffffu, isLast, 0);
        if (isLast) {
            __threadfence();
            volatile float* v1 = g_t1;
            volatile float* v2 = g_t2;
            volatile int*   vt = g_ct;
            volatile int*   vp = g_cp;
            const int i = lid;
            float t1 = v1[4*i] + v1[4*i+1] + v1[4*i+2] + v1[4*i+3];
            float t2 = v2[4*i] + v2[4*i+1] + v2[4*i+2] + v2[4*i+3];
            int   nt = vt[4*i] + vt[4*i+1] + vt[4*i+2] + vt[4*i+3];
            int   np = vp[4*i] + vp[4*i+1] + vp[4*i+2] + vp[4*i+3];
            float v = (nt > 0 && np > 0) ? (t1 + t2) / (2.0f * (float)nt) : 0.0f;
            #pragma unroll
            for (int o = 16; o > 0; o >>= 1)
                v += __shfl_xor_sync(0xffffffffu, v, o);
            if (lid == 0) {
                out[0] = v / (float)ITEMS;
                __threadfence();
                g_done = 0;               // reset for next graph replay
            }
        }
    }
}

extern "C" void kernel_launch(void* const* d_in, const int* in_sizes, int n_in,
                              void* d_out, int out_size)
{
    const float* pred   = (const float*)d_in[0];
    const float* target = (const float*)d_in[1];
    float* out = (float*)d_out;
    (void)in_sizes; (void)n_in; (void)out_size;

    bahl_fused_kernel<<<4 * ITEMS, NT>>>(pred, target, out);
}